// round 17
// baseline (speedup 1.0000x reference)
#include <cuda_runtime.h>
#include <cuda_fp16.h>
#include <cstdint>

#define MMEM 8192
#define FDIM 512
#define NQ   32768
#define EPSD 1e-12f

#define BM 64
#define BN 256
#define BK 32
#define NTH 256
#define NTK (MMEM / BK)     // 256 k-tiles

// ---- smem byte offsets (3-stage) ----
// A[stage]: 64 rows x 80B (32 fp16 + 16B pad) = 5120 per stage
#define SM_A    0
#define A_BUF   5120
// B[stage]: 32 rows x 512B (256 fp16) = 16384 per stage
#define SM_B    15360
#define B_BUF   16384
#define SM_RED  64512       // 4*64 floats
#define SM_FIN  65536       // 64 floats
#define SMEM_TOTAL 65792

// ---------------- device scratch ----------------
__device__ float4 g_posn[MMEM];
__device__ float4 g_embn[MMEM];
__device__ float4 g_pos4[MMEM];
__device__ float4 g_npe[MMEM];
__device__ float  g_memory[MMEM * FDIM];
__device__ __half g_FT[MMEM * FDIM];
__device__ __half g_MT[MMEM * FDIM];

// ---------------- PTX helpers ----------------
__device__ __forceinline__ uint32_t smem_u32(const void* p) {
    uint32_t a;
    asm("{ .reg .u64 t; cvta.to.shared.u64 t, %1; cvt.u32.u64 %0, t; }" : "=r"(a) : "l"(p));
    return a;
}
__device__ __forceinline__ void ldsm_x4(uint32_t* r, uint32_t addr) {
    asm volatile("ldmatrix.sync.aligned.m8n8.x4.shared.b16 {%0,%1,%2,%3}, [%4];"
        : "=r"(r[0]), "=r"(r[1]), "=r"(r[2]), "=r"(r[3]) : "r"(addr));
}
__device__ __forceinline__ void ldsm_x4t(uint32_t* r, uint32_t addr) {
    asm volatile("ldmatrix.sync.aligned.m8n8.x4.trans.shared.b16 {%0,%1,%2,%3}, [%4];"
        : "=r"(r[0]), "=r"(r[1]), "=r"(r[2]), "=r"(r[3]) : "r"(addr));
}
__device__ __forceinline__ void mma16816(float* c, const uint32_t* a, const uint32_t* b) {
    asm volatile("mma.sync.aligned.m16n8k16.row.col.f32.f16.f16.f32 "
        "{%0,%1,%2,%3}, {%4,%5,%6,%7}, {%8,%9}, {%0,%1,%2,%3};"
        : "+f"(c[0]), "+f"(c[1]), "+f"(c[2]), "+f"(c[3])
        : "r"(a[0]), "r"(a[1]), "r"(a[2]), "r"(a[3]), "r"(b[0]), "r"(b[1]));
}
// one-op packed fp32x2 -> fp16x2
__device__ __forceinline__ uint32_t cvt_f16x2(float lo, float hi) {
    uint32_t r;
    asm("cvt.rn.f16x2.f32 %0, %1, %2;" : "=r"(r) : "f"(hi), "f"(lo));
    return r;
}
__device__ __forceinline__ void cp16(uint32_t dst, const void* src) {
    asm volatile("cp.async.cg.shared.global [%0], [%1], 16;" :: "r"(dst), "l"(src) : "memory");
}
#define CP_COMMIT() asm volatile("cp.async.commit_group;" ::: "memory")
#define CP_WAIT1()  asm volatile("cp.async.wait_group 1;" ::: "memory")
#define CP_WAIT0()  asm volatile("cp.async.wait_group 0;" ::: "memory")

// ---------------- prep: normalize ----------------
__global__ void prep_kernel(const float* __restrict__ pos, const float* __restrict__ emb) {
    int i = blockIdx.x * blockDim.x + threadIdx.x;
    if (i >= MMEM) return;
    float x = pos[3 * i], y = pos[3 * i + 1], z = pos[3 * i + 2];
    float inv = rsqrtf(x * x + y * y + z * z);
    g_posn[i] = make_float4(x * inv, y * inv, z * inv, 0.f);
    g_pos4[i] = make_float4(x, y, z, 0.f);
    float a = emb[3 * i], b = emb[3 * i + 1], c = emb[3 * i + 2];
    float inv2 = rsqrtf(a * a + b * b + c * c);
    g_embn[i] = make_float4(a * inv2, b * inv2, c * inv2, 0.f);
}

// ---------------- convert: fp32[k][n] -> fp16 [k][n] ----------------
template <int SRC>
__global__ void split_kernel(const float* __restrict__ srcArg) {
    int id = blockIdx.x * blockDim.x + threadIdx.x;   // MMEM*FDIM/8 threads
    const float4* S = (const float4*)((SRC == 0) ? srcArg : (const float*)g_memory);
    __half* Dh = (SRC == 0) ? g_FT : g_MT;
    float4 v0 = S[id * 2], v1 = S[id * 2 + 1];
    uint32_t ph[4];
    ph[0] = cvt_f16x2(v0.x, v0.y);
    ph[1] = cvt_f16x2(v0.z, v0.w);
    ph[2] = cvt_f16x2(v1.x, v1.y);
    ph[3] = cvt_f16x2(v1.z, v1.w);
    *(uint4*)&Dh[(size_t)id * 8] = make_uint4(ph[0], ph[1], ph[2], ph[3]);
}

// ---------------- new_pos_emb (self-normalizing, 8 rows/block) ----------------
__global__ void posemb_kernel() {
    const int i0 = blockIdx.x * 8;
    const int t = threadIdx.x;
    float4 pn[8];
#pragma unroll
    for (int r = 0; r < 8; r++) pn[r] = g_posn[i0 + r];
    float ax[8] = {}, ay[8] = {}, az[8] = {}, as[8] = {};
    for (int j = t; j < MMEM; j += 256) {
        float4 en = g_embn[j];
        float4 p = g_pos4[j];
#pragma unroll
        for (int r = 0; r < 8; r++) {
            float w = __expf(pn[r].x * en.x + pn[r].y * en.y + pn[r].z * en.z);
            ax[r] = fmaf(w, p.x, ax[r]);
            ay[r] = fmaf(w, p.y, ay[r]);
            az[r] = fmaf(w, p.z, az[r]);
            as[r] += w;
        }
    }
    __shared__ float red[8][4][8];
    const int lane = t & 31, warp = t >> 5;
#pragma unroll
    for (int r = 0; r < 8; r++) {
        float v[4] = {ax[r], ay[r], az[r], as[r]};
#pragma unroll
        for (int c = 0; c < 4; c++) {
#pragma unroll
            for (int s = 16; s > 0; s >>= 1) v[c] += __shfl_down_sync(0xffffffffu, v[c], s);
            if (lane == 0) red[r][c][warp] = v[c];
        }
    }
    __syncthreads();
    if (t < 8) {
        float sx = 0, sy = 0, sz = 0, ss = 0;
#pragma unroll
        for (int w = 0; w < 8; w++) { sx += red[t][0][w]; sy += red[t][1][w]; sz += red[t][2][w]; ss += red[t][3][w]; }
        float inv = 1.0f / ss;
        float x = sx * inv, y = sy * inv, z = sz * inv;
        g_npe[i0 + t] = make_float4(x, y, z, x * x + y * y + z * z);
    }
}

// ---------------- fused softmax-GEMM on mma.sync (HMMA) ----------------
// 3-stage cp.async pipeline: two load groups always in flight, wait_group 1.
// C[BM x BN] = rownorm(Wfp16) @ Bfp16; exact fp32 row sums of unrounded weights.
template <int MODE>
__global__ __launch_bounds__(NTH, 2)
void mma_gemm(const float* __restrict__ qraw, float* __restrict__ CoutQ) {
    extern __shared__ __align__(1024) char smem[];
    const uint32_t sb = smem_u32(smem);
    const int tid = threadIdx.x;
    const int wid = tid >> 5, lane = tid & 31;
    const int row0 = (blockIdx.x >> 1) * BM;
    const int n0   = (blockIdx.x & 1) * BN;

    // weight-gen mapping: row = tid&63, k-group = (tid>>6)*8 + j (8 per thread)
    const int wr = tid & 63;
    const int kq = tid >> 6;      // 0..3

    float4 q;
    if (MODE == 0) {
        q = g_posn[row0 + wr];
    } else {
        int r = row0 + wr;
        float x = qraw[3 * r], y = qraw[3 * r + 1], z = qraw[3 * r + 2];
        q = make_float4(x, y, z, x * x + y * y + z * z);
    }
    const float4* kp_arr = (MODE == 0) ? g_embn : g_npe;
    const __half* Bg = (MODE == 0) ? g_FT : g_MT;

    // ldmatrix lane offsets
    const uint32_t arow  = (uint32_t)((lane & 15) * 80 + (lane >> 4) * 16);
    const uint32_t bkoff = (uint32_t)((lane & 7) * 512 + ((lane >> 3) & 1) * 4096);
    const uint32_t bxor  = (uint32_t)((lane & 7) << 4);
    const uint32_t bnb   = (uint32_t)(wid * 64 + (lane >> 4) * 16);   // warp's 32-col strip

    float acc[4][4][4];     // [m16 subtile][n8 subtile][frag]
#pragma unroll
    for (int a = 0; a < 4; a++)
#pragma unroll
        for (int b = 0; b < 4; b++)
#pragma unroll
            for (int c = 0; c < 4; c++) acc[a][b][c] = 0.f;
    float s_part = 0.f;

    // fill stage: issue B cp.async (+commit) and write A weights
    auto fill = [&](int kt, int stg) {
        const int k0 = kt * BK;
        const uint32_t base = sb + SM_B + stg * B_BUF;
#pragma unroll
        for (int i = 0; i < 4; i++) {
            int c = tid + i * NTH;            // 0..1023
            int k = c >> 5, n8 = c & 31;
            uint32_t dst = base + (uint32_t)(k * 512 + ((n8 * 16) ^ ((k & 7) << 4)));
            cp16(dst, Bg + (size_t)(k0 + k) * FDIM + n0 + n8 * 8);
        }
        CP_COMMIT();
        // weights: 8 per thread; fp32 sum + packed cvt
        uint32_t hp[4];
#pragma unroll
        for (int j2 = 0; j2 < 4; j2++) {
            float w0, w1;
#pragma unroll
            for (int u = 0; u < 2; u++) {
                float4 kp = __ldg(&kp_arr[k0 + kq * 8 + j2 * 2 + u]);
                float d = fmaf(q.x, kp.x, fmaf(q.y, kp.y, q.z * kp.z));
                float w;
                if (MODE == 0) w = __expf(d);
                else           w = __expf(-sqrtf(fmaxf(q.w + kp.w - 2.f * d, EPSD)));
                if (u == 0) w0 = w; else w1 = w;
            }
            s_part += w0 + w1;
            hp[j2] = cvt_f16x2(w0, w1);
        }
        *(uint4*)(smem + SM_A + stg * A_BUF + wr * 80 + kq * 16) =
            make_uint4(hp[0], hp[1], hp[2], hp[3]);
    };

    // prologue: stages 0,1 in flight
    fill(0, 0);
    fill(1, 1);

    int stg  = 0;   // stage of tile t
    int stg2 = 2;   // stage of tile t+2
    for (int kt = 0; kt < NTK; kt++) {
        CP_WAIT1();          // tile kt's B landed (only kt+1 may be pending)
        __syncthreads();     // A[kt] + B[kt] visible to all warps

        if (kt + 2 < NTK) fill(kt + 2, stg2);
        else              CP_COMMIT();          // keep wait-group count aligned

        const uint32_t Abase = sb + SM_A + stg * A_BUF;
        const uint32_t Bbase = sb + SM_B + stg * B_BUF;
#pragma unroll
        for (int kk = 0; kk < 2; kk++) {
            uint32_t bh[2][4];
#pragma unroll
            for (int p = 0; p < 2; p++) {
                uint32_t byte0 = (bnb + p * 32) ^ bxor;
                ldsm_x4t(bh[p], Bbase + kk * 8192 + bkoff + byte0);
            }
            uint32_t ah[4][4];
#pragma unroll
            for (int mi = 0; mi < 4; mi++)
                ldsm_x4(ah[mi], Abase + mi * 1280 + kk * 32 + arow);
#pragma unroll
            for (int mi = 0; mi < 4; mi++)
#pragma unroll
                for (int p = 0; p < 2; p++)
#pragma unroll
                    for (int qn = 0; qn < 2; qn++)
                        mma16816(acc[mi][p * 2 + qn], ah[mi], &bh[p][qn * 2]);
        }
        stg  = (stg  == 2) ? 0 : stg  + 1;
        stg2 = (stg2 == 2) ? 0 : stg2 + 1;
    }
    CP_WAIT0();

    // exact fp32 row sums -> inverse
    *(float*)(smem + SM_RED + (kq * 64 + wr) * 4) = s_part;
    __syncthreads();
    if (tid < BM) {
        float s = 0.f;
#pragma unroll
        for (int k = 0; k < 4; k++) s += *(float*)(smem + SM_RED + (k * 64 + tid) * 4);
        *(float*)(smem + SM_FIN + tid * 4) = 1.0f / s;
    }
    __syncthreads();

    // epilogue: warp covers rows mi*16 + {lane>>2, +8}, cols wid*32 + ni*8
    float* Cbase = (MODE == 0) ? g_memory : CoutQ;
    const int ncol0 = n0 + wid * 32 + (lane & 3) * 2;
#pragma unroll
    for (int mi = 0; mi < 4; mi++) {
        int r0 = mi * 16 + (lane >> 2);
        int r1 = r0 + 8;
        float inv0 = *(float*)(smem + SM_FIN + r0 * 4);
        float inv1 = *(float*)(smem + SM_FIN + r1 * 4);
        float* C0 = Cbase + (size_t)(row0 + r0) * FDIM + ncol0;
        float* C1 = Cbase + (size_t)(row0 + r1) * FDIM + ncol0;
#pragma unroll
        for (int ni = 0; ni < 4; ni++) {
            *(float2*)(C0 + ni * 8) = make_float2(acc[mi][ni][0] * inv0, acc[mi][ni][1] * inv0);
            *(float2*)(C1 + ni * 8) = make_float2(acc[mi][ni][2] * inv1, acc[mi][ni][3] * inv1);
        }
    }
}

// ---------------- launch ----------------
extern "C" void kernel_launch(void* const* d_in, const int* in_sizes, int n_in,
                              void* d_out, int out_size) {
    (void)in_sizes; (void)n_in; (void)out_size;
    const float* features  = (const float*)d_in[0];  // [8192, 512]
    const float* positions = (const float*)d_in[1];  // [8192, 3]
    const float* queries   = (const float*)d_in[2];  // [32768, 3]
    const float* pemb      = (const float*)d_in[3];  // [8192, 3]

    cudaFuncSetAttribute(mma_gemm<0>, cudaFuncAttributeMaxDynamicSharedMemorySize, SMEM_TOTAL);
    cudaFuncSetAttribute(mma_gemm<1>, cudaFuncAttributeMaxDynamicSharedMemorySize, SMEM_TOTAL);

    prep_kernel<<<MMEM / 256, 256>>>(positions, pemb);
    split_kernel<0><<<(MMEM * FDIM / 8) / 256, 256>>>(features);
    posemb_kernel<<<MMEM / 8, 256>>>();
    mma_gemm<0><<<(MMEM / BM) * 2, NTH, SMEM_TOTAL>>>(nullptr, nullptr);
    split_kernel<1><<<(MMEM * FDIM / 8) / 256, 256>>>(nullptr);
    mma_gemm<1><<<(NQ / BM) * 2, NTH, SMEM_TOTAL>>>(queries, (float*)d_out);
}